// round 1
// baseline (speedup 1.0000x reference)
#include <cuda_runtime.h>

// ---------------------------------------------------------------------------
// YoloLoss: full reduction over [N=32768, H=6, W=8, C=14] fp32 tensors.
// One thread = one (n,h,w) cell (14 channels). Block stages its 256 cells
// (2 x 14336 B) through shared memory with coalesced float4 loads, computes
// per-cell loss, block-reduces, and atomicAdd's a double scratch scalar.
// ---------------------------------------------------------------------------

#define CELL_F 14
#define TPB 256
#define FLOATS_PER_BLOCK (TPB * CELL_F)   // 3584 floats per tensor per block
#define VEC4_PER_BLOCK (FLOATS_PER_BLOCK / 4)  // 896

#define LAMBDA_COORD 8.0f
#define LAMBDA_CLASS 0.7f
#define EPS_IOU 1e-10f

__device__ double g_yolo_acc;

__global__ void yolo_zero_kernel() {
    g_yolo_acc = 0.0;
}

__device__ __forceinline__ float warp_reduce_sum(float v) {
    #pragma unroll
    for (int off = 16; off > 0; off >>= 1)
        v += __shfl_down_sync(0xFFFFFFFFu, v, off);
    return v;
}

__global__ void __launch_bounds__(TPB)
yolo_main_kernel(const float* __restrict__ pred,
                 const float* __restrict__ gt,
                 long long total_elems)
{
    __shared__ float so[FLOATS_PER_BLOCK];
    __shared__ float sg[FLOATS_PER_BLOCK];

    const long long base = (long long)blockIdx.x * FLOATS_PER_BLOCK;

    // ---- coalesced float4 staging (total_elems is a multiple of 4) ----
    {
        const float4* p4 = reinterpret_cast<const float4*>(pred + base);
        const float4* g4 = reinterpret_cast<const float4*>(gt + base);
        const long long rem4 = (total_elems - base) >> 2;  // float4s left
        float4* so4 = reinterpret_cast<float4*>(so);
        float4* sg4 = reinterpret_cast<float4*>(sg);
        #pragma unroll
        for (int i = threadIdx.x; i < VEC4_PER_BLOCK; i += TPB) {
            if ((long long)i < rem4) {
                so4[i] = p4[i];
                sg4[i] = g4[i];
            }
        }
    }
    __syncthreads();

    // ---- per-cell loss ----
    float contrib = 0.0f;
    const long long cells = total_elems / CELL_F;
    const long long cell = (long long)blockIdx.x * TPB + threadIdx.x;

    if (cell < cells) {
        const float* o = &so[threadIdx.x * CELL_F];
        const float* g = &sg[threadIdx.x * CELL_F];

        const float obj_flag = g[4];  // exactly 0.0f or 1.0f
        if (obj_flag > 0.0f) {
            // gt reference box (box 0 of gt)
            const float gx = g[0], gy = g[1];
            const float gw = g[2] * g[2], gh = g[3] * g[3];
            const float garea = gw * gh;

            float iou[2];
            #pragma unroll
            for (int b = 0; b < 2; b++) {
                const float x = o[5 * b + 0];
                const float y = o[5 * b + 1];
                const float w = o[5 * b + 2] * o[5 * b + 2];
                const float h = o[5 * b + 3] * o[5 * b + 3];
                const float left  = fmaxf(x - 0.5f * w, gx - 0.5f * gw);
                const float right = fminf(x + 0.5f * w, gx + 0.5f * gw);
                const float top   = fmaxf(y - 0.5f * h, gy - 0.5f * gh);
                const float bot   = fminf(y + 0.5f * h, gy + 0.5f * gh);
                const float inter = fmaxf(right - left, 0.0f) * fmaxf(bot - top, 0.0f);
                const float uni   = w * h + garea - inter;
                iou[b] = inter / (uni + EPS_IOU);
            }
            // jnp.argmax picks FIRST max -> responsible=1 only on strict >
            const int idx = (iou[1] > iou[0]) ? 1 : 0;
            const float max_iou = fmaxf(iou[0], iou[1]);

            const float* pr = o + 5 * idx;       // responsible pred box
            const float* po = o + 5 * (1 - idx); // other pred box
            const float* gr = g + 5 * idx;
            const float* go = g + 5 * (1 - idx);

            float loc = 0.0f;
            #pragma unroll
            for (int c = 0; c < 4; c++) {
                const float d = pr[c] - gr[c];
                loc = fmaf(d, d, loc);
            }
            const float dc = pr[4] - max_iou;
            const float conf = dc * dc;
            const float dn = po[4] - go[4];
            const float nobox = dn * dn;

            float cls = 0.0f;
            #pragma unroll
            for (int c = 10; c < 14; c++) {
                const float d = o[c] - g[c];
                cls = fmaf(d, d, cls);
            }
            contrib = conf + LAMBDA_COORD * loc + nobox + LAMBDA_CLASS * cls;
        } else {
            const float d4 = o[4] - g[4];
            const float d9 = o[9] - g[9];
            contrib = d4 * d4 + d9 * d9;  // LAMBDA_NOOBJ = 1
        }
    }

    // ---- block reduction ----
    __shared__ float warp_sums[TPB / 32];
    float v = warp_reduce_sum(contrib);
    const int wid = threadIdx.x >> 5;
    const int lid = threadIdx.x & 31;
    if (lid == 0) warp_sums[wid] = v;
    __syncthreads();
    if (wid == 0) {
        float s = (lid < TPB / 32) ? warp_sums[lid] : 0.0f;
        s = warp_reduce_sum(s);
        if (lid == 0) atomicAdd(&g_yolo_acc, (double)s);
    }
}

__global__ void yolo_finalize_kernel(float* __restrict__ out, long long n_batch) {
    out[0] = (float)(g_yolo_acc / (double)n_batch);
}

extern "C" void kernel_launch(void* const* d_in, const int* in_sizes, int n_in,
                              void* d_out, int out_size)
{
    const float* pred = (const float*)d_in[0];   // 'output'
    const float* gt   = (const float*)d_in[1];   // 'ground_truth'
    float* out = (float*)d_out;

    const long long total_elems = (long long)in_sizes[0];     // N*H*W*C
    const long long cells = total_elems / CELL_F;             // N*H*W
    const long long n_batch = total_elems / (6LL * 8 * CELL_F); // N
    const int grid = (int)((cells + TPB - 1) / TPB);          // 6144

    yolo_zero_kernel<<<1, 1>>>();
    yolo_main_kernel<<<grid, TPB>>>(pred, gt, total_elems);
    yolo_finalize_kernel<<<1, 1>>>(out, n_batch);
}